// round 8
// baseline (speedup 1.0000x reference)
#include <cuda_runtime.h>
#include <cuda_fp16.h>
#include <mma.h>
using namespace nvcuda;

#define NNODES 50000
#define NEDGES 1600000
#define ETOT   (NEDGES + NNODES)
#define DH     128

// ---------------- scratch (static device globals; no allocations) ----------
__device__ __half2 g_hh[NNODES * (DH / 2)];   // fp16 transformed features (gather payload)
__device__ __half2 g_xh[NNODES * (DH / 2)];   // fp16 layer outputs (GEMM A input)
__device__ float   g_ssrc[NNODES];            // exp(h . att_src)
__device__ float   g_sdst[NNODES];            // exp(h . att_dst)
__device__ int     g_rowptr[NNODES + 1];
__device__ int     g_cnt[NNODES];             // zero-init; self-cleaned each run by k_scan
__device__ int     g_srcs[ETOT];
__device__ int     g_eoff[ETOT];

// ---------------- helpers ---------------------------------------------------
__device__ __forceinline__ unsigned long long f32x2_dup(float x) {
    unsigned long long r;
    unsigned u = __float_as_uint(x);
    asm("mov.b64 %0, {%1, %1};" : "=l"(r) : "r"(u));
    return r;
}
__device__ __forceinline__ void fma2(unsigned long long& acc,
                                     unsigned long long a, unsigned long long b) {
    asm("fma.rn.f32x2 %0, %1, %2, %0;" : "+l"(acc) : "l"(a), "l"(b));
}
__device__ __forceinline__ void add2(unsigned long long& acc, unsigned long long o) {
    asm("add.rn.f32x2 %0, %1, %2;" : "=l"(acc) : "l"(acc), "l"(o));
}
__device__ __forceinline__ unsigned long long pk2(float lo, float hi) {
    unsigned long long r;
    asm("mov.b64 %0, {%1, %2};" : "=l"(r) : "r"(__float_as_uint(lo)), "r"(__float_as_uint(hi)));
    return r;
}
__device__ __forceinline__ float f2lo(unsigned long long v) {
    return __uint_as_float((unsigned)v);
}
__device__ __forceinline__ float f2hi(unsigned long long v) {
    return __uint_as_float((unsigned)(v >> 32));
}

// ---------------- CSR build ------------------------------------------------
// Requires g_cnt == 0 at entry (static zero-init; k_scan re-zeroes it each run).
__global__ void k_hist(const int* __restrict__ ei, int E, int n) {
    int i = blockIdx.x * blockDim.x + threadIdx.x;
    if (i >= E + n) return;
    int d = (i < E) ? ei[E + i] : (i - E);
    g_eoff[i] = atomicAdd(&g_cnt[d], 1);
}

// Single-block full scan: g_cnt (counts) -> g_rowptr (exclusive prefix).
// Also zeroes g_cnt for the next invocation and writes g_rowptr[n].
__global__ void __launch_bounds__(1024) k_scan(int n) {
    __shared__ int wsum[32];
    int t = threadIdx.x, lane = t & 31, w = t >> 5;
    int ch = (n + 1023) / 1024;
    int s = t * ch, e = min(s + ch, n);

    int sum = 0;
    for (int i = s; i < e; i++) sum += g_cnt[i];

    int x = sum;
    #pragma unroll
    for (int o = 1; o < 32; o <<= 1) {
        int y = __shfl_up_sync(0xffffffffu, x, o);
        if (lane >= o) x += y;
    }
    if (lane == 31) wsum[w] = x;
    __syncthreads();
    if (w == 0) {
        int v = wsum[lane];
        int xx = v;
        #pragma unroll
        for (int o = 1; o < 32; o <<= 1) {
            int y = __shfl_up_sync(0xffffffffu, xx, o);
            if (lane >= o) xx += y;
        }
        wsum[lane] = xx;   // inclusive
    }
    __syncthreads();
    int off = ((w == 0) ? 0 : wsum[w - 1]) + x - sum;   // exclusive thread offset

    int run = off;
    for (int i = s; i < e; i++) {
        int c = g_cnt[i];
        g_rowptr[i] = run;
        run += c;
        g_cnt[i] = 0;      // self-clean for next run
    }
    if (s < n && e == n) g_rowptr[n] = run;
}

// atomic-free scatter
__global__ void k_scatter(const int* __restrict__ ei, int E, int n) {
    int i = blockIdx.x * blockDim.x + threadIdx.x;
    if (i >= E + n) return;
    int s, d;
    if (i < E) { s = ei[i]; d = ei[E + i]; }
    else       { s = i - E; d = s; }
    g_srcs[g_rowptr[d] + g_eoff[i]] = s;
}

// ---------------- HMMA GEMM: C[nrows,COLS] = A[nrows,128] @ B[128,COLS] -----
// Block: 256 threads (8 warps), tile 128 rows x COLS. K staged in 64-slices.
// SVEC=true : writes fp16 features to g_hh + fused exp'd attention dots.
// SVEC=false: writes fp32 C with bias.
// A_HALF    : A is __half2 (g_xh) vs fp32 (converted while staging).
template <int COLS, bool SVEC, bool A_HALF>
__global__ void __launch_bounds__(256)
k_wgemm(const void* __restrict__ Aptr, const float* __restrict__ B,
        const float* __restrict__ bias, float* __restrict__ C,
        const float* __restrict__ asrc, const float* __restrict__ adst,
        int nrows) {
    const int NT = COLS / 16;
    const int BLD = COLS + 8;
    __shared__ __align__(16) __half As[128][72];    // 128 rows x 64 k
    __shared__ __align__(16) __half Bs[64][BLD];    // 64 k x COLS

    int tid = threadIdx.x;
    int w = tid >> 5, lane = tid & 31;
    int row0 = blockIdx.x * 128;

    wmma::fragment<wmma::accumulator, 16, 16, 16, float> acc[NT];
    #pragma unroll
    for (int nt = 0; nt < NT; nt++) wmma::fill_fragment(acc[nt], 0.f);

    for (int k0 = 0; k0 < 128; k0 += 64) {
        if (A_HALF) {
            const uint4* A16 = (const uint4*)Aptr;
            for (int idx = tid; idx < 128 * 8; idx += 256) {
                int r = idx >> 3, q = idx & 7;
                uint4 v = make_uint4(0u, 0u, 0u, 0u);
                if (row0 + r < nrows) v = A16[(row0 + r) * 16 + (k0 >> 3) + q];
                *(uint4*)&As[r][q * 8] = v;
            }
        } else {
            const float4* A4 = (const float4*)Aptr;
            for (int idx = tid; idx < 128 * 16; idx += 256) {
                int r = idx >> 4, q = idx & 15;
                float4 v = make_float4(0.f, 0.f, 0.f, 0.f);
                if (row0 + r < nrows) v = A4[(row0 + r) * 32 + (k0 >> 2) + q];
                __half2 h0 = __floats2half2_rn(v.x, v.y);
                __half2 h1 = __floats2half2_rn(v.z, v.w);
                *(uint2*)&As[r][q * 4] = make_uint2(*(unsigned*)&h0, *(unsigned*)&h1);
            }
        }
        {
            const float4* B4 = (const float4*)B;
            const int Q = COLS / 4;
            for (int idx = tid; idx < 64 * Q; idx += 256) {
                int kk = idx / Q, q = idx % Q;
                float4 v = B4[(k0 + kk) * Q + q];
                __half2 h0 = __floats2half2_rn(v.x, v.y);
                __half2 h1 = __floats2half2_rn(v.z, v.w);
                *(uint2*)&Bs[kk][q * 4] = make_uint2(*(unsigned*)&h0, *(unsigned*)&h1);
            }
        }
        __syncthreads();

        #pragma unroll
        for (int kk = 0; kk < 4; kk++) {
            wmma::fragment<wmma::matrix_a, 16, 16, 16, __half, wmma::row_major> af;
            wmma::load_matrix_sync(af, &As[w * 16][kk * 16], 72);
            #pragma unroll
            for (int nt = 0; nt < NT; nt++) {
                wmma::fragment<wmma::matrix_b, 16, 16, 16, __half, wmma::row_major> bf;
                wmma::load_matrix_sync(bf, &Bs[kk * 16][nt * 16], BLD);
                wmma::mma_sync(acc[nt], af, bf, acc[nt]);
            }
        }
        __syncthreads();
    }

    // ---- epilogue ----
    float* scr = ((float*)As) + w * 320;
    int r = lane & 15, hs = lane >> 4;
    int grow = row0 + w * 16 + r;
    float ss = 0.f, sd = 0.f;

    #pragma unroll
    for (int nt = 0; nt < NT; nt++) {
        wmma::store_matrix_sync(scr, acc[nt], 20, wmma::mem_row_major);
        __syncwarp();
        float v[8];
        #pragma unroll
        for (int j = 0; j < 8; j++) v[j] = scr[r * 20 + hs * 8 + j];
        __syncwarp();

        if (SVEC) {
            if (grow < nrows) {
                __half2 h0 = __floats2half2_rn(v[0], v[1]);
                __half2 h1 = __floats2half2_rn(v[2], v[3]);
                __half2 h2 = __floats2half2_rn(v[4], v[5]);
                __half2 h3 = __floats2half2_rn(v[6], v[7]);
                *(uint4*)&g_hh[grow * 64 + nt * 8 + hs * 4] =
                    make_uint4(*(unsigned*)&h0, *(unsigned*)&h1,
                               *(unsigned*)&h2, *(unsigned*)&h3);
            }
            float4 a0 = ((const float4*)asrc)[nt * 4 + hs * 2];
            float4 a1 = ((const float4*)asrc)[nt * 4 + hs * 2 + 1];
            float4 d0 = ((const float4*)adst)[nt * 4 + hs * 2];
            float4 d1 = ((const float4*)adst)[nt * 4 + hs * 2 + 1];
            ss += v[0] * a0.x + v[1] * a0.y + v[2] * a0.z + v[3] * a0.w
                + v[4] * a1.x + v[5] * a1.y + v[6] * a1.z + v[7] * a1.w;
            sd += v[0] * d0.x + v[1] * d0.y + v[2] * d0.z + v[3] * d0.w
                + v[4] * d1.x + v[5] * d1.y + v[6] * d1.z + v[7] * d1.w;
        } else {
            if (grow < nrows) {
                float4 b0 = ((const float4*)bias)[nt * 4 + hs * 2];
                float4 b1 = ((const float4*)bias)[nt * 4 + hs * 2 + 1];
                ((float4*)C)[grow * (COLS / 4) + nt * 4 + hs * 2] =
                    make_float4(v[0] + b0.x, v[1] + b0.y, v[2] + b0.z, v[3] + b0.w);
                ((float4*)C)[grow * (COLS / 4) + nt * 4 + hs * 2 + 1] =
                    make_float4(v[4] + b1.x, v[5] + b1.y, v[6] + b1.z, v[7] + b1.w);
            }
        }
    }
    if (SVEC) {
        ss += __shfl_xor_sync(0xffffffffu, ss, 16);
        sd += __shfl_xor_sync(0xffffffffu, sd, 16);
        if (hs == 0 && grow < nrows) {
            // store EXP of the dots: exp(max(a+b,0)) == max(exp(a)*exp(b), 1)
            g_ssrc[grow] = __expf(ss);
            g_sdst[grow] = __expf(sd);
        }
    }
}

// ---------------- GAT aggregation -------------------------------------------
// warp per dst node; (src, w) staged in smem; 16-lane fp16 feature rows
// (LDG.128), 2 edges per inner iteration; fp32 f32x2 accumulation.
// One-pass softmax with factorized exp weights. Output fp16 -> g_xh.
__global__ void k_agg(const float* __restrict__ bias, int n, int do_relu) {
    __shared__ uint2 stage[8][32];
    int wid = threadIdx.x >> 5;
    int node = blockIdx.x * 8 + wid;
    if (node >= n) return;
    int lane = threadIdx.x & 31;
    int sub = lane & 15, grp = lane >> 4;
    int beg = g_rowptr[node], end = g_rowptr[node + 1];
    float esd = g_sdst[node];    // already exp()

    unsigned long long acc[4] = {0ULL, 0ULL, 0ULL, 0ULL};
    float dsum = 0.f;
    const uint4* hh4 = (const uint4*)g_hh;

    for (int base = beg; base < end; base += 32) {
        int j = base + lane;
        int sj = 0;
        float w = 0.f;
        if (j < end) {
            sj = g_srcs[j];
            w = fmaxf(g_ssrc[sj] * esd, 1.0f);   // = exp(relu(ssrc+sdst))
            dsum += w;
        }
        stage[wid][lane] = make_uint2((unsigned)sj, __float_as_uint(w));
        __syncwarp();
        int cnt = min(32, end - base);
        int t = 0;
        #pragma unroll 4
        for (; t + 2 <= cnt; t += 2) {
            uint2 sw = stage[wid][t + grp];
            unsigned long long wd = f32x2_dup(__uint_as_float(sw.y));
            uint4 hv = hh4[(unsigned)sw.x * 16u + sub];
            float2 f0 = __half22float2(*(__half2*)&hv.x);
            float2 f1 = __half22float2(*(__half2*)&hv.y);
            float2 f2 = __half22float2(*(__half2*)&hv.z);
            float2 f3 = __half22float2(*(__half2*)&hv.w);
            fma2(acc[0], pk2(f0.x, f0.y), wd);
            fma2(acc[1], pk2(f1.x, f1.y), wd);
            fma2(acc[2], pk2(f2.x, f2.y), wd);
            fma2(acc[3], pk2(f3.x, f3.y), wd);
        }
        if (t < cnt && grp == 0) {
            uint2 sw = stage[wid][t];
            unsigned long long wd = f32x2_dup(__uint_as_float(sw.y));
            uint4 hv = hh4[(unsigned)sw.x * 16u + sub];
            float2 f0 = __half22float2(*(__half2*)&hv.x);
            float2 f1 = __half22float2(*(__half2*)&hv.y);
            float2 f2 = __half22float2(*(__half2*)&hv.z);
            float2 f3 = __half22float2(*(__half2*)&hv.w);
            fma2(acc[0], pk2(f0.x, f0.y), wd);
            fma2(acc[1], pk2(f1.x, f1.y), wd);
            fma2(acc[2], pk2(f2.x, f2.y), wd);
            fma2(acc[3], pk2(f3.x, f3.y), wd);
        }
        __syncwarp();
    }

    #pragma unroll
    for (int i = 0; i < 4; i++) {
        unsigned long long o = __shfl_xor_sync(0xffffffffu, acc[i], 16);
        add2(acc[i], o);
    }
    #pragma unroll
    for (int o = 16; o > 0; o >>= 1)
        dsum += __shfl_xor_sync(0xffffffffu, dsum, o);

    float inv = 1.f / dsum;
    float o0, o1, o2, o3;
    if (grp == 0) {
        o0 = f2lo(acc[0]); o1 = f2hi(acc[0]);
        o2 = f2lo(acc[1]); o3 = f2hi(acc[1]);
    } else {
        o0 = f2lo(acc[2]); o1 = f2hi(acc[2]);
        o2 = f2lo(acc[3]); o3 = f2hi(acc[3]);
    }
    float4 bb = ((const float4*)bias)[sub * 2 + grp];
    float rx = o0 * inv + bb.x, ry = o1 * inv + bb.y;
    float rz = o2 * inv + bb.z, rw = o3 * inv + bb.w;
    if (do_relu) {
        rx = fmaxf(rx, 0.f); ry = fmaxf(ry, 0.f);
        rz = fmaxf(rz, 0.f); rw = fmaxf(rw, 0.f);
    }
    __half2 ha = __floats2half2_rn(rx, ry);
    __half2 hb = __floats2half2_rn(rz, rw);
    *(uint2*)&g_xh[node * 64 + (sub * 2 + grp) * 2] =
        make_uint2(*(unsigned*)&ha, *(unsigned*)&hb);
}

// ---------------- launch ----------------------------------------------------
extern "C" void kernel_launch(void* const* d_in, const int* in_sizes, int n_in,
                              void* d_out, int out_size) {
    const float* node_x = (const float*)d_in[0];
    const int*   ei     = (const int*)d_in[1];
    const float* W1  = (const float*)d_in[2];
    const float* as1 = (const float*)d_in[3];
    const float* ad1 = (const float*)d_in[4];
    const float* b1  = (const float*)d_in[5];
    const float* W2  = (const float*)d_in[6];
    const float* as2 = (const float*)d_in[7];
    const float* ad2 = (const float*)d_in[8];
    const float* b2  = (const float*)d_in[9];
    const float* Wo  = (const float*)d_in[10];
    const float* bo  = (const float*)d_in[11];
    float* out = (float*)d_out;

    int n = in_sizes[0] / 128;
    int E = in_sizes[1] / 2;
    int tot = E + n;

    __half2* xh;
    cudaGetSymbolAddress((void**)&xh, g_xh);

    // CSR build (3 kernels; g_cnt is zero at entry, re-zeroed by k_scan)
    k_hist<<<(tot + 255) / 256, 256>>>(ei, E, n);
    k_scan<<<1, 1024>>>(n);
    k_scatter<<<(tot + 255) / 256, 256>>>(ei, E, n);

    int gblocks = (n + 127) / 128;
    int wblocks = (n + 7) / 8;

    // layer 1: HMMA GEMM (fp32 A converted) + fused exp'd attention dots
    k_wgemm<128, true, false><<<gblocks, 256>>>(node_x, W1, nullptr, nullptr, as1, ad1, n);
    k_agg<<<wblocks, 256>>>(b1, n, 1);

    // layer 2: HMMA GEMM (fp16 A from agg)
    k_wgemm<128, true, true><<<gblocks, 256>>>(xh, W2, nullptr, nullptr, as2, ad2, n);
    k_agg<<<wblocks, 256>>>(b2, n, 0);

    // output linear: HMMA GEMM (fp16 A), fp32 out + bias
    k_wgemm<64, false, true><<<gblocks, 256>>>(xh, Wo, bo, out, nullptr, nullptr, n);
}

// round 9
// speedup vs baseline: 1.2516x; 1.2516x over previous
#include <cuda_runtime.h>
#include <cuda_fp16.h>
#include <mma.h>
using namespace nvcuda;

#define NNODES 50000
#define NEDGES 1600000
#define ETOT   (NEDGES + NNODES)
#define DH     128

// ---------------- scratch (static device globals; no allocations) ----------
__device__ __half2 g_hh[NNODES * (DH / 2)];   // fp16 transformed features (gather payload)
__device__ __half2 g_xh[NNODES * (DH / 2)];   // fp16 layer outputs (GEMM A input)
__device__ float   g_ssrc[NNODES];            // exp(h . att_src)
__device__ float   g_sdst[NNODES];            // exp(h . att_dst)
__device__ int     g_rowptr[NNODES + 1];
__device__ int     g_cnt[NNODES];             // zero-init; re-zeroed by k_scan3 each run
__device__ int     g_bsum[260];
__device__ int     g_srcs[ETOT];
__device__ int     g_eoff[ETOT];

// ---------------- helpers ---------------------------------------------------
__device__ __forceinline__ unsigned long long f32x2_dup(float x) {
    unsigned long long r;
    unsigned u = __float_as_uint(x);
    asm("mov.b64 %0, {%1, %1};" : "=l"(r) : "r"(u));
    return r;
}
__device__ __forceinline__ void fma2(unsigned long long& acc,
                                     unsigned long long a, unsigned long long b) {
    asm("fma.rn.f32x2 %0, %1, %2, %0;" : "+l"(acc) : "l"(a), "l"(b));
}
__device__ __forceinline__ void add2(unsigned long long& acc, unsigned long long o) {
    asm("add.rn.f32x2 %0, %1, %2;" : "=l"(acc) : "l"(acc), "l"(o));
}
__device__ __forceinline__ unsigned long long pk2(float lo, float hi) {
    unsigned long long r;
    asm("mov.b64 %0, {%1, %2};" : "=l"(r) : "r"(__float_as_uint(lo)), "r"(__float_as_uint(hi)));
    return r;
}
__device__ __forceinline__ float f2lo(unsigned long long v) {
    return __uint_as_float((unsigned)v);
}
__device__ __forceinline__ float f2hi(unsigned long long v) {
    return __uint_as_float((unsigned)(v >> 32));
}

// ---------------- CSR build ------------------------------------------------
// Requires g_cnt == 0 at entry (static zero-init; k_scan3 re-zeroes it).
__global__ void k_hist(const int* __restrict__ ei, int E, int n) {
    int i = blockIdx.x * blockDim.x + threadIdx.x;
    if (i >= E + n) return;
    int d = (i < E) ? ei[E + i] : (i - E);
    g_eoff[i] = atomicAdd(&g_cnt[d], 1);
}

// phase 1: per-block exclusive scan of 256 counts -> partial rowptr + block sum
__global__ void k_scan1(int n) {
    __shared__ int wsum[8];
    int t = threadIdx.x, lane = t & 31, w = t >> 5;
    int i = blockIdx.x * 256 + t;
    int v = (i < n) ? g_cnt[i] : 0;
    int x = v;
    #pragma unroll
    for (int o = 1; o < 32; o <<= 1) {
        int y = __shfl_up_sync(0xffffffffu, x, o);
        if (lane >= o) x += y;
    }
    if (lane == 31) wsum[w] = x;
    __syncthreads();
    if (w == 0) {
        int s = (lane < 8) ? wsum[lane] : 0;
        #pragma unroll
        for (int o = 1; o < 8; o <<= 1) {
            int y = __shfl_up_sync(0xffffffffu, s, o);
            if (lane >= o) s += y;
        }
        if (lane < 8) wsum[lane] = s;
    }
    __syncthreads();
    int woff = (w == 0) ? 0 : wsum[w - 1];
    if (i < n) g_rowptr[i] = woff + x - v;
    if (t == 255) g_bsum[blockIdx.x] = wsum[7];
}

// phase 2: single warp exclusive-scans the block sums
__global__ void k_scan2(int nb) {
    int lane = threadIdx.x;
    int carry = 0;
    for (int base = 0; base < nb; base += 32) {
        int v = (base + lane < nb) ? g_bsum[base + lane] : 0;
        int x = v;
        #pragma unroll
        for (int o = 1; o < 32; o <<= 1) {
            int y = __shfl_up_sync(0xffffffffu, x, o);
            if (lane >= o) x += y;
        }
        if (base + lane < nb) g_bsum[base + lane] = carry + x - v;
        carry += __shfl_sync(0xffffffffu, x, 31);
    }
    if (lane == 0) g_bsum[nb] = carry;
}

// phase 3: add block offsets; zero g_cnt (self-clean); write rowptr[n]
__global__ void k_scan3(int n, int nb) {
    int i = blockIdx.x * 256 + threadIdx.x;
    if (i < n) {
        g_rowptr[i] += g_bsum[blockIdx.x];
        g_cnt[i] = 0;
    }
    if (i == 0) g_rowptr[n] = g_bsum[nb];
}

// atomic-free scatter
__global__ void k_scatter(const int* __restrict__ ei, int E, int n) {
    int i = blockIdx.x * blockDim.x + threadIdx.x;
    if (i >= E + n) return;
    int s, d;
    if (i < E) { s = ei[i]; d = ei[E + i]; }
    else       { s = i - E; d = s; }
    g_srcs[g_rowptr[d] + g_eoff[i]] = s;
}

// ---------------- HMMA GEMM: C[nrows,COLS] = A[nrows,128] @ B[128,COLS] -----
// 256 threads (8 warps), tile 128 rows x COLS, FULL K=128 staged once
// (dynamic smem), single __syncthreads, then 8x(NT) uninterrupted wmma ops.
// SVEC=true : writes fp16 features to g_hh + fused exp'd attention dots.
// SVEC=false: writes fp32 C with bias.
// A_HALF    : A is __half2 (g_xh) vs fp32 (converted while staging).
#define ALD 136
template <int COLS, bool SVEC, bool A_HALF>
__global__ void __launch_bounds__(256, 2)
k_wgemm(const void* __restrict__ Aptr, const float* __restrict__ B,
        const float* __restrict__ bias, float* __restrict__ C,
        const float* __restrict__ asrc, const float* __restrict__ adst,
        int nrows) {
    const int NT = COLS / 16;
    const int BLD = COLS + 8;
    extern __shared__ __align__(16) char dyn[];
    __half (*As)[ALD] = (__half(*)[ALD])dyn;                       // 128 x 128 k
    __half (*Bs)[BLD] = (__half(*)[BLD])(dyn + 128 * ALD * 2);     // 128 k x COLS

    int tid = threadIdx.x;
    int w = tid >> 5, lane = tid & 31;
    int row0 = blockIdx.x * 128;

    wmma::fragment<wmma::accumulator, 16, 16, 16, float> acc[NT];
    #pragma unroll
    for (int nt = 0; nt < NT; nt++) wmma::fill_fragment(acc[nt], 0.f);

    // --- stage A (full K=128) ---
    if (A_HALF) {
        const uint4* A16 = (const uint4*)Aptr;   // 16 uint4 per 128-half row
        for (int idx = tid; idx < 128 * 16; idx += 256) {
            int r = idx >> 4, q = idx & 15;
            uint4 v = make_uint4(0u, 0u, 0u, 0u);
            if (row0 + r < nrows) v = A16[(row0 + r) * 16 + q];
            *(uint4*)&As[r][q * 8] = v;
        }
    } else {
        const float4* A4 = (const float4*)Aptr;  // 32 float4 per 128-f32 row
        for (int idx = tid; idx < 128 * 32; idx += 256) {
            int r = idx >> 5, q = idx & 31;
            float4 v = make_float4(0.f, 0.f, 0.f, 0.f);
            if (row0 + r < nrows) v = A4[(row0 + r) * 32 + q];
            __half2 h0 = __floats2half2_rn(v.x, v.y);
            __half2 h1 = __floats2half2_rn(v.z, v.w);
            *(uint2*)&As[r][q * 4] = make_uint2(*(unsigned*)&h0, *(unsigned*)&h1);
        }
    }
    // --- stage B (full K=128 x COLS, fp32 -> fp16) ---
    {
        const float4* B4 = (const float4*)B;
        const int Q = COLS / 4;
        for (int idx = tid; idx < 128 * Q; idx += 256) {
            int kk = idx / Q, q = idx % Q;
            float4 v = B4[kk * Q + q];
            __half2 h0 = __floats2half2_rn(v.x, v.y);
            __half2 h1 = __floats2half2_rn(v.z, v.w);
            *(uint2*)&Bs[kk][q * 4] = make_uint2(*(unsigned*)&h0, *(unsigned*)&h1);
        }
    }
    __syncthreads();

    #pragma unroll
    for (int kk = 0; kk < 8; kk++) {
        wmma::fragment<wmma::matrix_a, 16, 16, 16, __half, wmma::row_major> af;
        wmma::load_matrix_sync(af, &As[w * 16][kk * 16], ALD);
        #pragma unroll
        for (int nt = 0; nt < NT; nt++) {
            wmma::fragment<wmma::matrix_b, 16, 16, 16, __half, wmma::row_major> bf;
            wmma::load_matrix_sync(bf, &Bs[kk * 16][nt * 16], BLD);
            wmma::mma_sync(acc[nt], af, bf, acc[nt]);
        }
    }
    __syncthreads();   // As reused as epilogue scratch below

    // ---- epilogue: per-warp scratch 16x20 floats ----
    float* scr = ((float*)dyn) + w * 320;
    int r = lane & 15, hs = lane >> 4;
    int grow = row0 + w * 16 + r;
    float ss = 0.f, sd = 0.f;

    #pragma unroll
    for (int nt = 0; nt < NT; nt++) {
        wmma::store_matrix_sync(scr, acc[nt], 20, wmma::mem_row_major);
        __syncwarp();
        float v[8];
        #pragma unroll
        for (int j = 0; j < 8; j++) v[j] = scr[r * 20 + hs * 8 + j];
        __syncwarp();

        if (SVEC) {
            if (grow < nrows) {
                __half2 h0 = __floats2half2_rn(v[0], v[1]);
                __half2 h1 = __floats2half2_rn(v[2], v[3]);
                __half2 h2 = __floats2half2_rn(v[4], v[5]);
                __half2 h3 = __floats2half2_rn(v[6], v[7]);
                *(uint4*)&g_hh[grow * 64 + nt * 8 + hs * 4] =
                    make_uint4(*(unsigned*)&h0, *(unsigned*)&h1,
                               *(unsigned*)&h2, *(unsigned*)&h3);
            }
            float4 a0 = ((const float4*)asrc)[nt * 4 + hs * 2];
            float4 a1 = ((const float4*)asrc)[nt * 4 + hs * 2 + 1];
            float4 d0 = ((const float4*)adst)[nt * 4 + hs * 2];
            float4 d1 = ((const float4*)adst)[nt * 4 + hs * 2 + 1];
            ss += v[0] * a0.x + v[1] * a0.y + v[2] * a0.z + v[3] * a0.w
                + v[4] * a1.x + v[5] * a1.y + v[6] * a1.z + v[7] * a1.w;
            sd += v[0] * d0.x + v[1] * d0.y + v[2] * d0.z + v[3] * d0.w
                + v[4] * d1.x + v[5] * d1.y + v[6] * d1.z + v[7] * d1.w;
        } else {
            if (grow < nrows) {
                float4 b0 = ((const float4*)bias)[nt * 4 + hs * 2];
                float4 b1 = ((const float4*)bias)[nt * 4 + hs * 2 + 1];
                ((float4*)C)[grow * (COLS / 4) + nt * 4 + hs * 2] =
                    make_float4(v[0] + b0.x, v[1] + b0.y, v[2] + b0.z, v[3] + b0.w);
                ((float4*)C)[grow * (COLS / 4) + nt * 4 + hs * 2 + 1] =
                    make_float4(v[4] + b1.x, v[5] + b1.y, v[6] + b1.z, v[7] + b1.w);
            }
        }
    }
    if (SVEC) {
        ss += __shfl_xor_sync(0xffffffffu, ss, 16);
        sd += __shfl_xor_sync(0xffffffffu, sd, 16);
        if (hs == 0 && grow < nrows) {
            // store EXP of the dots: exp(max(a+b,0)) == max(exp(a)*exp(b), 1)
            g_ssrc[grow] = __expf(ss);
            g_sdst[grow] = __expf(sd);
        }
    }
}

// ---------------- GAT aggregation -------------------------------------------
// warp per dst node; (src, w) staged in smem; 16-lane fp16 feature rows
// (LDG.128), 2 edges per inner iteration; fp32 f32x2 accumulation.
// One-pass softmax with factorized exp weights. Output fp16 -> g_xh.
__global__ void k_agg(const float* __restrict__ bias, int n, int do_relu) {
    __shared__ uint2 stage[8][32];
    int wid = threadIdx.x >> 5;
    int node = blockIdx.x * 8 + wid;
    if (node >= n) return;
    int lane = threadIdx.x & 31;
    int sub = lane & 15, grp = lane >> 4;
    int beg = g_rowptr[node], end = g_rowptr[node + 1];
    float esd = g_sdst[node];    // already exp()

    unsigned long long acc[4] = {0ULL, 0ULL, 0ULL, 0ULL};
    float dsum = 0.f;
    const uint4* hh4 = (const uint4*)g_hh;

    for (int base = beg; base < end; base += 32) {
        int j = base + lane;
        int sj = 0;
        float w = 0.f;
        if (j < end) {
            sj = g_srcs[j];
            w = fmaxf(g_ssrc[sj] * esd, 1.0f);   // = exp(relu(ssrc+sdst))
            dsum += w;
        }
        stage[wid][lane] = make_uint2((unsigned)sj, __float_as_uint(w));
        __syncwarp();
        int cnt = min(32, end - base);
        int t = 0;
        #pragma unroll 4
        for (; t + 2 <= cnt; t += 2) {
            uint2 sw = stage[wid][t + grp];
            unsigned long long wd = f32x2_dup(__uint_as_float(sw.y));
            uint4 hv = hh4[(unsigned)sw.x * 16u + sub];
            float2 f0 = __half22float2(*(__half2*)&hv.x);
            float2 f1 = __half22float2(*(__half2*)&hv.y);
            float2 f2 = __half22float2(*(__half2*)&hv.z);
            float2 f3 = __half22float2(*(__half2*)&hv.w);
            fma2(acc[0], pk2(f0.x, f0.y), wd);
            fma2(acc[1], pk2(f1.x, f1.y), wd);
            fma2(acc[2], pk2(f2.x, f2.y), wd);
            fma2(acc[3], pk2(f3.x, f3.y), wd);
        }
        if (t < cnt && grp == 0) {
            uint2 sw = stage[wid][t];
            unsigned long long wd = f32x2_dup(__uint_as_float(sw.y));
            uint4 hv = hh4[(unsigned)sw.x * 16u + sub];
            float2 f0 = __half22float2(*(__half2*)&hv.x);
            float2 f1 = __half22float2(*(__half2*)&hv.y);
            float2 f2 = __half22float2(*(__half2*)&hv.z);
            float2 f3 = __half22float2(*(__half2*)&hv.w);
            fma2(acc[0], pk2(f0.x, f0.y), wd);
            fma2(acc[1], pk2(f1.x, f1.y), wd);
            fma2(acc[2], pk2(f2.x, f2.y), wd);
            fma2(acc[3], pk2(f3.x, f3.y), wd);
        }
        __syncwarp();
    }

    #pragma unroll
    for (int i = 0; i < 4; i++) {
        unsigned long long o = __shfl_xor_sync(0xffffffffu, acc[i], 16);
        add2(acc[i], o);
    }
    #pragma unroll
    for (int o = 16; o > 0; o >>= 1)
        dsum += __shfl_xor_sync(0xffffffffu, dsum, o);

    float inv = 1.f / dsum;
    float o0, o1, o2, o3;
    if (grp == 0) {
        o0 = f2lo(acc[0]); o1 = f2hi(acc[0]);
        o2 = f2lo(acc[1]); o3 = f2hi(acc[1]);
    } else {
        o0 = f2lo(acc[2]); o1 = f2hi(acc[2]);
        o2 = f2lo(acc[3]); o3 = f2hi(acc[3]);
    }
    float4 bb = ((const float4*)bias)[sub * 2 + grp];
    float rx = o0 * inv + bb.x, ry = o1 * inv + bb.y;
    float rz = o2 * inv + bb.z, rw = o3 * inv + bb.w;
    if (do_relu) {
        rx = fmaxf(rx, 0.f); ry = fmaxf(ry, 0.f);
        rz = fmaxf(rz, 0.f); rw = fmaxf(rw, 0.f);
    }
    __half2 ha = __floats2half2_rn(rx, ry);
    __half2 hb = __floats2half2_rn(rz, rw);
    *(uint2*)&g_xh[node * 64 + (sub * 2 + grp) * 2] =
        make_uint2(*(unsigned*)&ha, *(unsigned*)&hb);
}

// ---------------- launch ----------------------------------------------------
extern "C" void kernel_launch(void* const* d_in, const int* in_sizes, int n_in,
                              void* d_out, int out_size) {
    const float* node_x = (const float*)d_in[0];
    const int*   ei     = (const int*)d_in[1];
    const float* W1  = (const float*)d_in[2];
    const float* as1 = (const float*)d_in[3];
    const float* ad1 = (const float*)d_in[4];
    const float* b1  = (const float*)d_in[5];
    const float* W2  = (const float*)d_in[6];
    const float* as2 = (const float*)d_in[7];
    const float* ad2 = (const float*)d_in[8];
    const float* b2  = (const float*)d_in[9];
    const float* Wo  = (const float*)d_in[10];
    const float* bo  = (const float*)d_in[11];
    float* out = (float*)d_out;

    int n = in_sizes[0] / 128;
    int E = in_sizes[1] / 2;
    int tot = E + n;
    int nb = (n + 255) / 256;

    __half2* xh;
    cudaGetSymbolAddress((void**)&xh, g_xh);

    // dynamic smem sizes (full-K staging)
    const int SM128 = 128 * ALD * 2 + 128 * (128 + 8) * 2;   // 69632
    const int SM64  = 128 * ALD * 2 + 128 * (64 + 8) * 2;    // 53248
    cudaFuncSetAttribute(k_wgemm<128, true, false>,
                         cudaFuncAttributeMaxDynamicSharedMemorySize, SM128);
    cudaFuncSetAttribute(k_wgemm<128, true, true>,
                         cudaFuncAttributeMaxDynamicSharedMemorySize, SM128);
    cudaFuncSetAttribute(k_wgemm<64, false, true>,
                         cudaFuncAttributeMaxDynamicSharedMemorySize, SM64);

    // CSR build (g_cnt is zero at entry, re-zeroed by k_scan3)
    k_hist<<<(tot + 255) / 256, 256>>>(ei, E, n);
    k_scan1<<<nb, 256>>>(n);
    k_scan2<<<1, 32>>>(nb);
    k_scan3<<<nb, 256>>>(n, nb);
    k_scatter<<<(tot + 255) / 256, 256>>>(ei, E, n);

    int gblocks = (n + 127) / 128;
    int wblocks = (n + 7) / 8;

    // layer 1: HMMA GEMM (fp32 A converted) + fused exp'd attention dots
    k_wgemm<128, true, false><<<gblocks, 256, SM128>>>(node_x, W1, nullptr, nullptr, as1, ad1, n);
    k_agg<<<wblocks, 256>>>(b1, n, 1);

    // layer 2: HMMA GEMM (fp16 A from agg)
    k_wgemm<128, true, true><<<gblocks, 256, SM128>>>(xh, W2, nullptr, nullptr, as2, ad2, n);
    k_agg<<<wblocks, 256>>>(b2, n, 0);

    // output linear: HMMA GEMM (fp16 A), fp32 out + bias
    k_wgemm<64, false, true><<<gblocks, 256, SM64>>>(xh, Wo, bo, out, nullptr, nullptr, n);
}